// round 12
// baseline (speedup 1.0000x reference)
#include <cuda_runtime.h>
#include <cstdint>

typedef unsigned long long u64;

// ---------- f32x2 / MUFU helpers ----------
__device__ __forceinline__ u64 ffma2(u64 a, u64 b, u64 c) {
    u64 d;
    asm("fma.rn.f32x2 %0, %1, %2, %3;" : "=l"(d) : "l"(a), "l"(b), "l"(c));
    return d;
}
__device__ __forceinline__ u64 fpack(float x, float y) {
    u64 d;
    asm("mov.b64 %0, {%1, %2};" : "=l"(d) : "r"(__float_as_uint(x)), "r"(__float_as_uint(y)));
    return d;
}
__device__ __forceinline__ void funpack(u64 v, float& x, float& y) {
    unsigned int a, b;
    asm("mov.b64 {%0, %1}, %2;" : "=r"(a), "=r"(b) : "l"(v));
    x = __uint_as_float(a);
    y = __uint_as_float(b);
}
__device__ __forceinline__ float flo(u64 v) {
    unsigned int a, b;
    asm("mov.b64 {%0, %1}, %2;" : "=r"(a), "=r"(b) : "l"(v));
    return __uint_as_float(a);
}
__device__ __forceinline__ float fex2(float x) {
    float r; asm("ex2.approx.f32 %0, %1;" : "=f"(r) : "f"(x)); return r;
}
__device__ __forceinline__ float frcp(float x) {
    float r; asm("rcp.approx.f32 %0, %1;" : "=f"(r) : "f"(x)); return r;
}
__device__ __forceinline__ float ftanha(float x) {
    float r; asm("tanh.approx.f32 %0, %1;" : "=f"(r) : "f"(x)); return r;
}
__device__ __forceinline__ float fsig_exact(float x) {
    return frcp(1.0f + fex2(-1.44269504f * x));
}
__device__ __forceinline__ float ftanh_exact(float x) {
    return fmaf(-2.0f, frcp(1.0f + fex2(2.88539008f * x)), 1.0f);
}

// ---------- problem constants ----------
constexpr int BATCH = 8192;
constexpr int HID   = 10;
constexpr int STEPS = 512;
constexpr int WPB   = 19;
constexpr int TPB   = WPB * 32;        // 608
constexpr int GRID  = 148;             // exactly 1 block / SM
constexpr int TOTW  = GRID * WPB;      // 2812 warps; elem slot s of warp g -> g + s*2812

// Folded weights: G = w_ih @ l2_w @ l1_w (30x10), d = w_ih@l2_b + (w_ih@l2_w)@l1_b + b_ih (30)
__device__ float g_G[300];
__device__ float g_d[30];
// sink rows for lanes without a valid batch element (branch-free stores)
__device__ float g_sink[STEPS * HID];

// ---------- prep kernel: fold the input path ----------
__global__ void prep_kernel(const float* __restrict__ w_ih,
                            const float* __restrict__ b_ih,
                            const float* __restrict__ l1_w,
                            const float* __restrict__ l1_b,
                            const float* __restrict__ l2_w,
                            const float* __restrict__ l2_b) {
    __shared__ float Wm[300]; // w_ih @ l2_w : (30,10)
    int t = threadIdx.x;
    if (t < 300) {
        int r = t / 10, m = t % 10;
        float s = 0.0f;
        for (int i = 0; i < 64; i++) s += w_ih[r * 64 + i] * l2_w[i * 10 + m];
        Wm[t] = s;
    }
    __syncthreads();
    if (t < 300) {
        int r = t / 10, k = t % 10;
        float g = 0.0f;
        for (int m = 0; m < 10; m++) g += Wm[r * 10 + m] * l1_w[m * 10 + k];
        g_G[t] = g;
    } else if (t < 330) {
        int r = t - 300;
        float s = b_ih[r];
        for (int i = 0; i < 64; i++) s += w_ih[r * 64 + i] * l2_b[i];
        for (int m = 0; m < 10; m++) s += Wm[r * 10 + m] * l1_b[m];
        g_d[r] = s;
    }
}

// ---------- main recurrence kernel ----------
// GATE-PACKED decomposition: thread = (ONE batch element, dim j). The f32x2
// lanes hold two GATES, not two elements: WRZ[k]=(Mr,Mz), WIH[k]=(Gn,Wn).
// h is stored DUPLICATED (h,h) in smem so one LDS.128 feeds the gate-paired
// FFMA2s directly. Per element-step: 20 FFMA2 + 10 scalar FFMA (O-dot) —
// 80 rt-weighted fma-pipe cycles vs 125 for element-packing — and 2x the
// warps (2731, 4.6/SMSP) for latency/MUFU overlap. 3 elements per warp on
// lanes 0..29; lanes 30/31 shadow slot 0 and store to a sink. Barrier-free
// exchange (convergent warp, LSU-ordered STS->LDS). sigma via tanh.approx
// with 0.5 folded into r/z weights.
__global__ void __launch_bounds__(TPB) gru_kernel(
    const float* __restrict__ hidden,
    const float* __restrict__ w_hh,
    const float* __restrict__ b_ih,
    const float* __restrict__ b_hh,
    const float* __restrict__ l1_w,
    const float* __restrict__ l1_b,
    float* __restrict__ out) {
    // [warp][buf][slot 0..3][dim]: (h,h) duplicated pairs; slot 3 = spare scratch
    __shared__ alignas(16) u64 hsh[WPB][2][4][HID];

    const int lane = threadIdx.x & 31;
    const int w    = threadIdx.x >> 5;
    const int p    = lane / 10;            // 0..2 element slots, 3 = spare lanes
    const int dd   = (p < 3) ? p : 0;      // spares read slot 0
    const int j    = lane - p * 10;        // 0..9 (spares: 0..1)
    const int g    = blockIdx.x * WPB + w;
    const int eIdx = g + dd * TOTW;        // round-robin element map
    const bool valid = (p < 3) && (eIdx < BATCH);
    const int eL   = valid ? eIdx : 0;

    // gate-packed weight rows: WRZ=(0.5*Mr, 0.5*Mz), WIH=(Gn, Wn), WO scalar
    u64 WRZ[10], WIH[10];
    float WO[10];
#pragma unroll
    for (int k = 0; k < 10; k++) {
        WRZ[k] = fpack(0.5f * (w_hh[j * 10 + k]        + g_G[j * 10 + k]),
                       0.5f * (w_hh[(10 + j) * 10 + k] + g_G[(10 + j) * 10 + k]));
        WIH[k] = fpack(g_G[(20 + j) * 10 + k], w_hh[(20 + j) * 10 + k]);
        WO[k]  = l1_w[j * 10 + k];
    }
    const u64 bRZ = fpack(0.5f * (b_hh[j] + g_d[j]),
                          0.5f * (b_hh[10 + j] + g_d[10 + j]));
    const u64 bIH = fpack(g_d[20 + j], b_hh[20 + j]);
    const float bO = l1_b[j];

    float h = hidden[eL * 10 + j];

    u64* wr0 = &hsh[w][0][p][j];
    u64* wr1 = &hsh[w][1][p][j];
    const ulonglong2* rd0 = reinterpret_cast<const ulonglong2*>(&hsh[w][0][dd][0]);
    const ulonglong2* rd1 = reinterpret_cast<const ulonglong2*>(&hsh[w][1][dd][0]);

    asm volatile("st.shared.v2.f32 [%0], {%1, %2};" :: "l"(wr0), "f"(h), "f"(h));
    __syncwarp();

    // peeled step 0: x0 = 0 -> gi = b_ih exactly (no G*h). Exact activations.
    {
        float aR = b_hh[j] + b_ih[j];
        float aZ = b_hh[10 + j] + b_ih[10 + j];
        float aH = b_hh[20 + j];
#pragma unroll
        for (int k = 0; k < 10; k++) {
            float hk = flo(hsh[w][0][dd][k]);
            aR = fmaf(w_hh[j * 10 + k], hk, aR);
            aZ = fmaf(w_hh[(10 + j) * 10 + k], hk, aZ);
            aH = fmaf(w_hh[(20 + j) * 10 + k], hk, aH);
        }
        float r = fsig_exact(aR);
        float z = fsig_exact(aZ);
        float n = ftanh_exact(fmaf(r, aH, b_ih[20 + j]));
        h = fmaf(z, h - n, n);
    }
    asm volatile("st.shared.v2.f32 [%0], {%1, %2};" :: "l"(wr1), "f"(h), "f"(h));
    __syncwarp();

    // REVERSE output: o_t -> row (511 - t); at iter t we emit o_{t-1}.
    float* o = valid
        ? out + (size_t)eIdx * (STEPS * HID) + (STEPS - 1) * HID + j
        : g_sink + (STEPS - 1) * HID + j;

    // one GRU step: read buffer RD ((h,h) pairs), write WRP, store o at OFS.
#define STEP(RD, WRP, OFS)                                                    \
  do {                                                                        \
    const ulonglong2 h01 = (RD)[0], h23 = (RD)[1], h45 = (RD)[2],             \
                     h67 = (RD)[3], h89 = (RD)[4];                            \
    u64 aRZ = bRZ, aIH = bIH;                                                 \
    float aO = bO, aO2 = 0.0f;                                                \
    aRZ = ffma2(WRZ[0], h01.x, aRZ);  aRZ = ffma2(WRZ[1], h01.y, aRZ);        \
    aRZ = ffma2(WRZ[2], h23.x, aRZ);  aRZ = ffma2(WRZ[3], h23.y, aRZ);        \
    aRZ = ffma2(WRZ[4], h45.x, aRZ);  aRZ = ffma2(WRZ[5], h45.y, aRZ);        \
    aRZ = ffma2(WRZ[6], h67.x, aRZ);  aRZ = ffma2(WRZ[7], h67.y, aRZ);        \
    aRZ = ffma2(WRZ[8], h89.x, aRZ);  aRZ = ffma2(WRZ[9], h89.y, aRZ);        \
    /* r-tanh as early as possible: it heads the serial path */               \
    float aR, aZ;                                                             \
    funpack(aRZ, aR, aZ);                                                     \
    const float tR = ftanha(aR);                                              \
    aIH = ffma2(WIH[0], h01.x, aIH);  aIH = ffma2(WIH[1], h01.y, aIH);        \
    aIH = ffma2(WIH[2], h23.x, aIH);  aIH = ffma2(WIH[3], h23.y, aIH);        \
    aIH = ffma2(WIH[4], h45.x, aIH);  aIH = ffma2(WIH[5], h45.y, aIH);        \
    aIH = ffma2(WIH[6], h67.x, aIH);  aIH = ffma2(WIH[7], h67.y, aIH);        \
    aIH = ffma2(WIH[8], h89.x, aIH);  aIH = ffma2(WIH[9], h89.y, aIH);        \
    float aI, aH;                                                             \
    funpack(aIH, aI, aH);                                                     \
    const float r = fmaf(0.5f, tR, 0.5f);                                     \
    const float n = ftanha(fmaf(r, aH, aI));                                  \
    aO  = fmaf(WO[0], flo(h01.x), aO);   aO2 = fmaf(WO[1], flo(h01.y), aO2);  \
    aO  = fmaf(WO[2], flo(h23.x), aO);   aO2 = fmaf(WO[3], flo(h23.y), aO2);  \
    aO  = fmaf(WO[4], flo(h45.x), aO);   aO2 = fmaf(WO[5], flo(h45.y), aO2);  \
    aO  = fmaf(WO[6], flo(h67.x), aO);   aO2 = fmaf(WO[7], flo(h67.y), aO2);  \
    aO  = fmaf(WO[8], flo(h89.x), aO);   aO2 = fmaf(WO[9], flo(h89.y), aO2);  \
    o[OFS] = aO + aO2;                                                        \
    const float z = fmaf(0.5f, ftanha(aZ), 0.5f);                             \
    h = fmaf(z, h - n, n);                                                    \
    asm volatile("st.shared.v2.f32 [%0], {%1, %2};" ::                        \
                 "l"(WRP), "f"(h), "f"(h));                                   \
  } while (0)

    // t = 1..510 as 255 double-steps; then t = 511. After step 0, h is in buf1.
#pragma unroll 1
    for (int c = 0; c < 255; ++c) {
        STEP(rd1, wr0, 0);      // odd t: read buf1, write buf0
        STEP(rd0, wr1, -10);    // even t: read buf0, write buf1
        o -= 2 * HID;
    }
    STEP(rd1, wr0, 0);          // t = 511

    // epilogue: o_511 -> row 0 (h_512 sits in buffer 0)
    __syncwarp();
    {
        float aO = bO, aO2 = 0.0f;
        const ulonglong2 h01 = rd0[0], h23 = rd0[1], h45 = rd0[2],
                         h67 = rd0[3], h89 = rd0[4];
        aO  = fmaf(WO[0], flo(h01.x), aO);   aO2 = fmaf(WO[1], flo(h01.y), aO2);
        aO  = fmaf(WO[2], flo(h23.x), aO);   aO2 = fmaf(WO[3], flo(h23.y), aO2);
        aO  = fmaf(WO[4], flo(h45.x), aO);   aO2 = fmaf(WO[5], flo(h45.y), aO2);
        aO  = fmaf(WO[6], flo(h67.x), aO);   aO2 = fmaf(WO[7], flo(h67.y), aO2);
        aO  = fmaf(WO[8], flo(h89.x), aO);   aO2 = fmaf(WO[9], flo(h89.y), aO2);
        o[-10] = aO + aO2;
    }
#undef STEP
}

extern "C" void kernel_launch(void* const* d_in, const int* in_sizes, int n_in,
                              void* d_out, int out_size) {
    const float* hidden = (const float*)d_in[0];
    const float* w_ih   = (const float*)d_in[1];
    const float* w_hh   = (const float*)d_in[2];
    const float* b_ih   = (const float*)d_in[3];
    const float* b_hh   = (const float*)d_in[4];
    const float* l1_w   = (const float*)d_in[5];
    const float* l1_b   = (const float*)d_in[6];
    const float* l2_w   = (const float*)d_in[7];
    const float* l2_b   = (const float*)d_in[8];

    prep_kernel<<<1, 384>>>(w_ih, b_ih, l1_w, l1_b, l2_w, l2_b);
    gru_kernel<<<GRID, TPB>>>(hidden, w_hh, b_ih, b_hh, l1_w, l1_b, (float*)d_out);
}

// round 13
// speedup vs baseline: 1.2149x; 1.2149x over previous
#include <cuda_runtime.h>
#include <cstdint>

typedef unsigned long long u64;

// ---------- f32x2 / MUFU helpers ----------
__device__ __forceinline__ u64 ffma2(u64 a, u64 b, u64 c) {
    u64 d;
    asm("fma.rn.f32x2 %0, %1, %2, %3;" : "=l"(d) : "l"(a), "l"(b), "l"(c));
    return d;
}
__device__ __forceinline__ u64 fadd2(u64 a, u64 b) {
    u64 d;
    asm("add.rn.f32x2 %0, %1, %2;" : "=l"(d) : "l"(a), "l"(b));
    return d;
}
__device__ __forceinline__ u64 fpack(float x, float y) {
    u64 d;
    asm("mov.b64 %0, {%1, %2};" : "=l"(d) : "r"(__float_as_uint(x)), "r"(__float_as_uint(y)));
    return d;
}
__device__ __forceinline__ u64 fdup(float s) { return fpack(s, s); }
__device__ __forceinline__ void funpack(u64 v, float& x, float& y) {
    unsigned int a, b;
    asm("mov.b64 {%0, %1}, %2;" : "=r"(a), "=r"(b) : "l"(v));
    x = __uint_as_float(a);
    y = __uint_as_float(b);
}
__device__ __forceinline__ float fex2(float x) {
    float r; asm("ex2.approx.f32 %0, %1;" : "=f"(r) : "f"(x)); return r;
}
__device__ __forceinline__ float frcp(float x) {
    float r; asm("rcp.approx.f32 %0, %1;" : "=f"(r) : "f"(x)); return r;
}
__device__ __forceinline__ float ftanha(float x) {
    float r; asm("tanh.approx.f32 %0, %1;" : "=f"(r) : "f"(x)); return r;
}
__device__ __forceinline__ float fsig_exact(float x) {
    return frcp(1.0f + fex2(-1.44269504f * x));
}
__device__ __forceinline__ float ftanh_exact(float x) {
    return fmaf(-2.0f, frcp(1.0f + fex2(2.88539008f * x)), 1.0f);
}

// ---------- problem constants ----------
constexpr int BATCH = 8192;
constexpr int HID   = 10;
constexpr int STEPS = 512;
constexpr int PAIRS = BATCH / 2;       // 4096
constexpr int WPB   = 9;
constexpr int TPB   = WPB * 32;        // 288
constexpr int GRID  = 152;             // GB300 has 152 SMs: exactly 1 block/SM
constexpr int TOTW  = GRID * WPB;      // 1368 warps >= 1366 needed (3 pairs/warp)

// Folded weights: G = w_ih @ l2_w @ l1_w (30x10), d = w_ih@l2_b + (w_ih@l2_w)@l1_b + b_ih (30)
__device__ float g_G[300];
__device__ float g_d[30];
// sink rows for lanes without a valid batch pair (branch-free stores)
__device__ float g_sink[2 * STEPS * HID];

// ---------- prep kernel: fold the input path ----------
__global__ void prep_kernel(const float* __restrict__ w_ih,
                            const float* __restrict__ b_ih,
                            const float* __restrict__ l1_w,
                            const float* __restrict__ l1_b,
                            const float* __restrict__ l2_w,
                            const float* __restrict__ l2_b) {
    __shared__ float Wm[300]; // w_ih @ l2_w : (30,10)
    int t = threadIdx.x;
    if (t < 300) {
        int r = t / 10, m = t % 10;
        float s = 0.0f;
        for (int i = 0; i < 64; i++) s += w_ih[r * 64 + i] * l2_w[i * 10 + m];
        Wm[t] = s;
    }
    __syncthreads();
    if (t < 300) {
        int r = t / 10, k = t % 10;
        float g = 0.0f;
        for (int m = 0; m < 10; m++) g += Wm[r * 10 + m] * l1_w[m * 10 + k];
        g_G[t] = g;
    } else if (t < 330) {
        int r = t - 300;
        float s = b_ih[r];
        for (int i = 0; i < 64; i++) s += w_ih[r * 64 + i] * l2_b[i];
        for (int m = 0; m < 10; m++) s += Wm[r * 10 + m] * l1_b[m];
        g_d[r] = s;
    }
}

// ---------- main recurrence kernel ----------
// R3-winning shape, re-gridded for GB300's 152 SMs: 152 blocks x 9 warps x
// 3 pairs = 4104 pair slots for 4096 pairs (near-perfect fit, least per-SM
// work possible for this mapping). thread = (batch pair, gate dim j);
// pair = 2 batch elements in f32x2 (pipe-sum optimal: 50 FFMA2 / 6 elems).
// Lanes 30/31 shadow slot 0, store to sink. h exchanged through warp-local
// double-buffered shared rows (LDS.128), one __syncwarp per step.
// sigma(a)=0.5+0.5*tanh(a/2) with the 0.5 folded into r/z weights; all loop
// activations tanh.approx.
__global__ void __launch_bounds__(TPB) gru_kernel(
    const float* __restrict__ hidden,
    const float* __restrict__ w_hh,
    const float* __restrict__ b_ih,
    const float* __restrict__ b_hh,
    const float* __restrict__ l1_w,
    const float* __restrict__ l1_b,
    float* __restrict__ out) {
    __shared__ alignas(16) u64 hsh[WPB][2][4][HID];

    const int lane = threadIdx.x & 31;
    const int w    = threadIdx.x >> 5;
    const int p    = lane / 10;            // 0..2 pair slots, 3 = spare lanes
    const int dd   = (p < 3) ? p : 0;      // spares read slot 0
    const int j    = lane - p * 10;        // 0..9 (spares: 0..1)
    const int g    = blockIdx.x * WPB + w;
    const int pairIdx = g + dd * TOTW;     // round-robin pair map
    const bool valid  = (p < 3) && (pairIdx < PAIRS);
    const int bb      = valid ? pairIdx * 2 : 0;

    // per-thread folded + scaled weight rows, duplicated into both f32x2 halves
    u64 Mr[10], Mz[10], Gn[10], Wn[10], L1[10];
#pragma unroll
    for (int k = 0; k < 10; k++) {
        Mr[k] = fdup(0.5f * (w_hh[j * 10 + k]        + g_G[j * 10 + k]));
        Mz[k] = fdup(0.5f * (w_hh[(10 + j) * 10 + k] + g_G[(10 + j) * 10 + k]));
        Gn[k] = fdup(g_G[(20 + j) * 10 + k]);
        Wn[k] = fdup(w_hh[(20 + j) * 10 + k]);
        L1[k] = fdup(l1_w[j * 10 + k]);
    }
    const u64 vbr  = fdup(0.5f * (b_hh[j]      + g_d[j]));
    const u64 vbz  = fdup(0.5f * (b_hh[10 + j] + g_d[10 + j]));
    const u64 vbin = fdup(g_d[20 + j]);
    const u64 vbhn = fdup(b_hh[20 + j]);
    const u64 vl1b = fdup(l1_b[j]);
    const u64 ZERO2 = 0ULL;
    const u64 HALF2 = fdup(0.5f);
    const u64 NEG12 = fdup(-1.0f);

    float hx = hidden[bb * 10 + j];
    float hy = hidden[(bb + 1) * 10 + j];

    // zero the spare slot so LDS.128 of slot 3 never reads garbage
    if (p == 0) { hsh[w][0][3][j] = 0ULL; hsh[w][1][3][j] = 0ULL; }
    hsh[w][0][p][j] = fpack(hx, hy);
    __syncwarp();

    // peeled step 0: x0 = 0 -> gi = b_ih exactly (no G*h term). Exact activations.
    {
        float aRx = b_hh[j] + b_ih[j];
        float aZx = b_hh[10 + j] + b_ih[10 + j];
        float aRy = aRx, aZy = aZx;
        float aHx = b_hh[20 + j], aHy = aHx;
#pragma unroll
        for (int k = 0; k < 10; k++) {
            float kx, ky;
            funpack(hsh[w][0][dd][k], kx, ky);
            float wr = w_hh[j * 10 + k];
            float wz = w_hh[(10 + j) * 10 + k];
            float wn = w_hh[(20 + j) * 10 + k];
            aRx = fmaf(wr, kx, aRx); aRy = fmaf(wr, ky, aRy);
            aZx = fmaf(wz, kx, aZx); aZy = fmaf(wz, ky, aZy);
            aHx = fmaf(wn, kx, aHx); aHy = fmaf(wn, ky, aHy);
        }
        float inb = b_ih[20 + j];
        float rx = fsig_exact(aRx), ry = fsig_exact(aRy);
        float zx = fsig_exact(aZx), zy = fsig_exact(aZy);
        float nx = ftanh_exact(fmaf(rx, aHx, inb));
        float ny = ftanh_exact(fmaf(ry, aHy, inb));
        hx = fmaf(zx, hx - nx, nx);
        hy = fmaf(zy, hy - ny, ny);
    }
    u64 hv = fpack(hx, hy);
    hsh[w][1][p][j] = hv;

    // REVERSE output: o_t -> row (511 - t); at iter t we emit o_{t-1} -> row 512 - t
    // invalid lanes walk a sink row instead (branch-free stores, in-bounds)
    float* o0;
    float* o1;
    if (valid) {
        o0 = out + (size_t)bb * (STEPS * HID) + (STEPS - 1) * HID + j;
        o1 = out + (size_t)(bb + 1) * (STEPS * HID) + (STEPS - 1) * HID + j;
    } else {
        o0 = g_sink + (STEPS - 1) * HID + j;
        o1 = g_sink + STEPS * HID + (STEPS - 1) * HID + j;
    }

#pragma unroll 2
    for (int t = 1; t < STEPS; ++t) {
        __syncwarp();
        const int rb = t & 1;
        const ulonglong2* hp = reinterpret_cast<const ulonglong2*>(&hsh[w][rb][dd][0]);
        // split chains for the two accumulators on the serial path
        u64 aR = vbr, aR2 = ZERO2;
        u64 aH = vbhn, aH2 = ZERO2;
        u64 aZ = vbz, aI = vbin, aO = vl1b;
#pragma unroll
        for (int kk = 0; kk < 5; kk++) {
            const ulonglong2 hh = hp[kk];           // LDS.128: h[2kk], h[2kk+1]
            const int k = 2 * kk;
            aR  = ffma2(Mr[k], hh.x, aR);   aR2 = ffma2(Mr[k + 1], hh.y, aR2);
            aH  = ffma2(Wn[k], hh.x, aH);   aH2 = ffma2(Wn[k + 1], hh.y, aH2);
            aZ  = ffma2(Mz[k], hh.x, aZ);   aZ  = ffma2(Mz[k + 1], hh.y, aZ);
            aI  = ffma2(Gn[k], hh.x, aI);   aI  = ffma2(Gn[k + 1], hh.y, aI);
            aO  = ffma2(L1[k], hh.x, aO);   aO  = ffma2(L1[k + 1], hh.y, aO);
        }
        aR = fadd2(aR, aR2);
        aH = fadd2(aH, aH2);

        // store o_{t-1} (aO computed from h_t which is h_new of step t-1)
        {
            float ox, oy;
            funpack(aO, ox, oy);
            *o0 = ox; *o1 = oy;
            o0 -= HID; o1 -= HID;
        }

        // r = 0.5 + 0.5*tanh(aR), z likewise (aR/aZ pre-scaled by 0.5)
        float aRx, aRy, aZx, aZy;
        funpack(aR, aRx, aRy);
        funpack(aZ, aZx, aZy);
        u64 rv = ffma2(HALF2, fpack(ftanha(aRx), ftanha(aRy)), HALF2);
        u64 zv = ffma2(HALF2, fpack(ftanha(aZx), ftanha(aZy)), HALF2);

        // n = tanh(aI + r*aH)
        u64 argv = ffma2(rv, aH, aI);
        float ax, ay;
        funpack(argv, ax, ay);
        u64 nv = fpack(ftanha(ax), ftanha(ay));

        // h' = n + z*(h - n)
        u64 dv = ffma2(nv, NEG12, hv);
        hv = ffma2(zv, dv, nv);
        hsh[w][rb ^ 1][p][j] = hv;
    }

    // epilogue: o_511 -> row 0 (h_512 sits in buffer 0 after t=511)
    __syncwarp();
    {
        u64 aO = vl1b;
#pragma unroll
        for (int k = 0; k < 10; k++) aO = ffma2(L1[k], hsh[w][0][dd][k], aO);
        float ox, oy;
        funpack(aO, ox, oy);
        *o0 = ox; *o1 = oy;
    }
}

extern "C" void kernel_launch(void* const* d_in, const int* in_sizes, int n_in,
                              void* d_out, int out_size) {
    const float* hidden = (const float*)d_in[0];
    const float* w_ih   = (const float*)d_in[1];
    const float* w_hh   = (const float*)d_in[2];
    const float* b_ih   = (const float*)d_in[3];
    const float* b_hh   = (const float*)d_in[4];
    const float* l1_w   = (const float*)d_in[5];
    const float* l1_b   = (const float*)d_in[6];
    const float* l2_w   = (const float*)d_in[7];
    const float* l2_b   = (const float*)d_in[8];

    prep_kernel<<<1, 384>>>(w_ih, b_ih, l1_w, l1_b, l2_w, l2_b);
    gru_kernel<<<GRID, TPB>>>(hidden, w_hh, b_ih, b_hh, l1_w, l1_b, (float*)d_out);
}